// round 5
// baseline (speedup 1.0000x reference)
#include <cuda_runtime.h>
#include <math.h>

#define Nn   4
#define MA   256
#define NFS  128
#define KK   8
#define HID  256
#define OUTD 32
#define RCf  5.0f
#define PIf  3.14159265358979323846f
#define ROWS (Nn*MA)   // 1024

// ---------------- scratch ---------------------------------------------------
__device__ float g_a[ROWS];
__device__ float g_b[ROWS];
__device__ float g_p[ROWS*HID];
__device__ float g_q[ROWS*HID];

// ---------------- kernel A: per-atom projections (+ output prefix) ---------
// grid = 256 (128 row-blocks of 8 rows x 2 col-halves), 128 threads.
// thread = 4 cols (vector weight loads) x 2 rows (register reuse).
__global__ void __launch_bounds__(128) kA(
        const float* __restrict__ h,
        const float* __restrict__ Wp1,
        const float* __restrict__ Wa,
        const int*   __restrict__ z,
        const float* __restrict__ r,
        float* __restrict__ out, int has_prefix) {
    __shared__ float hs[8*NFS];
    const int t    = threadIdx.x;
    const int row0 = (blockIdx.x >> 1) * 8;
    const int half = blockIdx.x & 1;

    {   // load 8 h rows (1024 floats) as float4
        const float4* hsrc = (const float4*)(h + (size_t)row0*NFS);
        float4* hdst = (float4*)hs;
        hdst[t]       = hsrc[t];
        hdst[t + 128] = hsrc[t + 128];
    }
    if (has_prefix) {
        const int gt = blockIdx.x * 128 + t;
        if (gt < ROWS)   out[gt] = (float)z[gt];
        if (gt < ROWS*3) out[ROWS + gt] = r[gt];
    }
    __syncthreads();

    const int cq  = t & 31;
    const int col = half*128 + cq*4;
    const int rw  = (t >> 5) * 2;          // rows rw, rw+1 within the 8

    float4 ap0 = {0,0,0,0}, ap1 = {0,0,0,0};
    float4 aq0 = {0,0,0,0}, aq1 = {0,0,0,0};

#pragma unroll 4
    for (int f = 0; f < NFS; f++) {
        const float4 wt = *(const float4*)&Wp1[(size_t)f*HID + col];
        const float4 wb = *(const float4*)&Wp1[(size_t)(NFS+f)*HID + col];
        const float h0 = hs[rw*NFS + f];
        const float h1 = hs[(rw+1)*NFS + f];
        ap0.x = fmaf(h0, wt.x, ap0.x); ap0.y = fmaf(h0, wt.y, ap0.y);
        ap0.z = fmaf(h0, wt.z, ap0.z); ap0.w = fmaf(h0, wt.w, ap0.w);
        ap1.x = fmaf(h1, wt.x, ap1.x); ap1.y = fmaf(h1, wt.y, ap1.y);
        ap1.z = fmaf(h1, wt.z, ap1.z); ap1.w = fmaf(h1, wt.w, ap1.w);
        aq0.x = fmaf(h0, wb.x, aq0.x); aq0.y = fmaf(h0, wb.y, aq0.y);
        aq0.z = fmaf(h0, wb.z, aq0.z); aq0.w = fmaf(h0, wb.w, aq0.w);
        aq1.x = fmaf(h1, wb.x, aq1.x); aq1.y = fmaf(h1, wb.y, aq1.y);
        aq1.z = fmaf(h1, wb.z, aq1.z); aq1.w = fmaf(h1, wb.w, aq1.w);
    }
    *(float4*)&g_p[(size_t)(row0+rw  )*HID + col] = ap0;
    *(float4*)&g_p[(size_t)(row0+rw+1)*HID + col] = ap1;
    *(float4*)&g_q[(size_t)(row0+rw  )*HID + col] = aq0;
    *(float4*)&g_q[(size_t)(row0+rw+1)*HID + col] = aq1;

    // a,b dots: only half==0 blocks; warp w handles rows 2w, 2w+1
    if (half == 0) {
        const int w = t >> 5, lane = t & 31;
        float sa0 = 0.f, sb0 = 0.f, sa1 = 0.f, sb1 = 0.f;
        for (int f = lane; f < NFS; f += 32) {
            const float wa0 = Wa[f], wa1 = Wa[NFS+f];
            const float h0 = hs[(2*w)*NFS + f];
            const float h1 = hs[(2*w+1)*NFS + f];
            sa0 = fmaf(h0, wa0, sa0); sb0 = fmaf(h0, wa1, sb0);
            sa1 = fmaf(h1, wa0, sa1); sb1 = fmaf(h1, wa1, sb1);
        }
#pragma unroll
        for (int off = 16; off; off >>= 1) {
            sa0 += __shfl_down_sync(0xffffffffu, sa0, off);
            sb0 += __shfl_down_sync(0xffffffffu, sb0, off);
            sa1 += __shfl_down_sync(0xffffffffu, sa1, off);
            sb1 += __shfl_down_sync(0xffffffffu, sb1, off);
        }
        if (lane == 0) {
            g_a[row0 + 2*w]     = sa0; g_b[row0 + 2*w]     = sb0;
            g_a[row0 + 2*w + 1] = sa1; g_b[row0 + 2*w + 1] = sb1;
        }
    }
}

// ---------------- kernel F: fused attention + topK + MLP + output ----------
// grid = 1024 (one block per row), 256 threads.
__global__ void __launch_bounds__(256) kF(
        const int*   __restrict__ z,
        const float* __restrict__ r,
        const float* __restrict__ ba_,
        const float* __restrict__ bp1,
        const float* __restrict__ Wp2,
        const float* __restrict__ bp2,
        float*       __restrict__ cout) {
    __shared__ float px[MA], py[MA], pz[MA], sbv[MA];
    __shared__ unsigned char smk[MA];
    __shared__ unsigned long long scand[64];
    __shared__ float wsum[8];
    __shared__ float satt[KK];
    __shared__ int   sidx[KK];
    __shared__ float sdx[KK], sdy[KK], sdz[KK];
    __shared__ __align__(16) float hidT[HID][KK];   // transposed: k contiguous
    __shared__ float sp[8*256];                     // per-tg matvec partials

    const int t   = threadIdx.x;
    const int row = blockIdx.x;
    const int n   = row >> 8;
    const int i   = row & (MA-1);
    const int bse = n * MA;
    const int j   = t;

    px[j]  = r[(size_t)(bse+j)*3 + 0];
    py[j]  = r[(size_t)(bse+j)*3 + 1];
    pz[j]  = r[(size_t)(bse+j)*3 + 2];
    smk[j] = (z[bse+j] > -1) ? 1 : 0;
    sbv[j] = g_b[bse+j];
    const float b1  = bp1[t];
    const float bav = ba_[0];
    const float av  = g_a[row];
    __syncthreads();

    // ---- attention score (fast math) ----
    const float dx = px[j]-px[i], dy = py[j]-py[i], dz = pz[j]-pz[i];
    const float d  = sqrtf(dx*dx + dy*dy + dz*dz);
    const bool  msk = smk[i] && smk[j] && (j != i);
    float g = 0.f;
    if (msk) {
        const float cf = 0.5f * (__cosf(fminf(d, RCf) * (PIf/RCf)) + 1.f);
        g = __expf(av + cf*sbv[j] + bav);
    }

    // ---- warp sums of g ----
    float s = g;
#pragma unroll
    for (int off = 16; off; off >>= 1) s += __shfl_xor_sync(0xffffffffu, s, off);
    if ((t & 31) == 0) wsum[t >> 5] = s;

    // ---- intra-warp exact full rank on unique u64 keys ----
    const unsigned long long key =
        (((unsigned long long)__float_as_uint(g)) << 32) | (unsigned)(MA-1-j);
    int rk = 0;
#pragma unroll
    for (int sft = 1; sft < 32; sft++) {
        const unsigned long long ok = __shfl_xor_sync(0xffffffffu, key, sft);
        rk += (ok > key);
    }
    if (rk < KK) scand[(t >> 5)*KK + rk] = key;
    __syncthreads();

    float sumg = 0.f;
#pragma unroll
    for (int w = 0; w < 8; w++) sumg += wsum[w];
    const float invsum = __fdividef(1.f, fmaxf(sumg, 1e-8f));

    // ---- warp 0: rank the 64 candidates, emit global top-8 ----
    if (t < 32) {
        const unsigned long long k0 = scand[t], k1 = scand[t + 32];
        int r0 = 0, r1 = 0;
#pragma unroll 8
        for (int m = 0; m < 64; m++) {
            const unsigned long long km = scand[m];
            r0 += (km > k0);
            r1 += (km > k1);
        }
#pragma unroll
        for (int pick = 0; pick < 2; pick++) {
            const unsigned long long kk = pick ? k1 : k0;
            const int rr = pick ? r1 : r0;
            if (rr < KK) {
                const int jw = MA - 1 - (int)(kk & 0xffffffffu);
                satt[rr] = __uint_as_float((unsigned)(kk >> 32)) * invsum;
                sidx[rr] = jw;
                const float ddx = px[jw]-px[i], ddy = py[jw]-py[i], ddz = pz[jw]-pz[i];
                const float dd  = sqrtf(ddx*ddx + ddy*ddy + ddz*ddz);
                const float inv = __fdividef(1.f, fmaxf(dd, 1e-4f));
                sdx[rr] = ddx*inv; sdy[rr] = ddy*inv; sdz[rr] = ddz*inv;
            }
        }
    }
    __syncthreads();

    // ---- MLP layer 1 -> hidT[t][k] (k contiguous) ----
    {
        const float pv = g_p[(size_t)row*HID + t];
        float xv[KK];
#pragma unroll
        for (int k = 0; k < KK; k++) {
            const float x = fmaf(satt[k], pv + g_q[(size_t)(bse + sidx[k])*HID + t], b1);
            xv[k] = __fdividef(x, 1.f + __expf(-x));   // silu
        }
        float4* dst = (float4*)&hidT[t][0];
        dst[0] = make_float4(xv[0], xv[1], xv[2], xv[3]);
        dst[1] = make_float4(xv[4], xv[5], xv[6], xv[7]);
    }
    __syncthreads();

    // ---- layer 2 matvec: thread = (o, tt-range of 32); weight loaded once,
    //      reused for all 8 k's via broadcast LDS.128 of hidT[tt][0..7] ----
    {
        const int o  = t & 31;
        const int tg = t >> 5;
        float acc[KK];
#pragma unroll
        for (int k = 0; k < KK; k++) acc[k] = 0.f;
#pragma unroll 8
        for (int u = 0; u < 32; u++) {
            const int tt = tg*32 + u;
            const float w = __ldg(&Wp2[(size_t)tt*OUTD + o]);
            const float4 h0 = *(const float4*)&hidT[tt][0];
            const float4 h1 = *(const float4*)&hidT[tt][4];
            acc[0] = fmaf(h0.x, w, acc[0]); acc[1] = fmaf(h0.y, w, acc[1]);
            acc[2] = fmaf(h0.z, w, acc[2]); acc[3] = fmaf(h0.w, w, acc[3]);
            acc[4] = fmaf(h1.x, w, acc[4]); acc[5] = fmaf(h1.y, w, acc[5]);
            acc[6] = fmaf(h1.z, w, acc[6]); acc[7] = fmaf(h1.w, w, acc[7]);
        }
#pragma unroll
        for (int k = 0; k < KK; k++) sp[tg*256 + k*32 + o] = acc[k];
    }
    __syncthreads();

    // ---- finalize: combine 8 partials, bias + direction, store ----
    {
        const int k = t >> 5;
        const int o = t & 31;
        float acc = bp2[o];
#pragma unroll
        for (int tg = 0; tg < 8; tg++) acc += sp[tg*256 + t];
        const size_t ob = ((size_t)(row*KK + k)*OUTD + o) * 3;
        cout[ob+0] = acc * sdx[k];
        cout[ob+1] = acc * sdy[k];
        cout[ob+2] = acc * sdz[k];
    }
}

// ---------------------------------------------------------------------------
extern "C" void kernel_launch(void* const* d_in, const int* in_sizes, int n_in,
                              void* d_out, int out_size) {
    const int*   z   = (const int*)  d_in[0];
    const float* r   = (const float*)d_in[1];
    const float* h   = (const float*)d_in[2];
    const float* Wa  = (const float*)d_in[3];
    const float* ba  = (const float*)d_in[4];
    const float* Wp1 = (const float*)d_in[5];
    const float* bp1 = (const float*)d_in[6];
    const float* Wp2 = (const float*)d_in[7];
    const float* bp2 = (const float*)d_in[8];

    float* out = (float*)d_out;
    const int CSZ  = Nn*MA*KK*OUTD*3;         // 786432
    const int PREF = ROWS + ROWS*3;           // 4096 (z + r)
    const int has_prefix = (out_size == CSZ + PREF) ? 1 : 0;
    float* cout = has_prefix ? (out + PREF) : out;

    kA<<<256,  128>>>(h, Wp1, Wa, z, r, out, has_prefix);
    kF<<<ROWS, 256>>>(z, r, ba, bp1, Wp2, bp2, cout);
}

// round 6
// speedup vs baseline: 1.2365x; 1.2365x over previous
#include <cuda_runtime.h>
#include <math.h>

#define Nn   4
#define MA   256
#define NFS  128
#define KK   8
#define HID  256
#define OUTD 32
#define RCf  5.0f
#define PIf  3.14159265358979323846f
#define ROWS (Nn*MA)   // 1024

// ---------------- scratch ---------------------------------------------------
__device__ float g_a[ROWS];
__device__ float g_b[ROWS];
__device__ float g_p[ROWS*HID];
__device__ float g_q[ROWS*HID];

// ---------------- kernel A: per-atom projections (+ output prefix) ---------
// grid = 128 blocks x 512 threads. Block = 8 rows x 256 cols (p and q).
// thread = col (t&255) x row-half (t>>8): 4 rows, 8 accumulators.
// Scalar coalesced weight loads; f unrolled x4 for 8-deep LDG MLP.
__global__ void __launch_bounds__(512) kA(
        const float* __restrict__ h,
        const float* __restrict__ Wp1,
        const float* __restrict__ Wa,
        const int*   __restrict__ z,
        const float* __restrict__ r,
        float* __restrict__ out, int has_prefix) {
    __shared__ float hs[8*NFS];
    const int t    = threadIdx.x;
    const int row0 = blockIdx.x * 8;

    if (t < 256) {   // load 8 h rows (1024 floats) as float4
        ((float4*)hs)[t] = ((const float4*)(h + (size_t)row0*NFS))[t];
    }
    if (has_prefix) {
        const int gt = blockIdx.x * 512 + t;
        if (gt < ROWS)   out[gt] = (float)z[gt];
        if (gt < ROWS*3) out[ROWS + gt] = r[gt];
    }
    __syncthreads();

    const int col = t & 255;
    const int rh  = t >> 8;            // 0/1 -> rows rh*4 .. rh*4+3
    const float* hrow = &hs[rh*4*NFS];

    float accp[4] = {0.f,0.f,0.f,0.f};
    float accq[4] = {0.f,0.f,0.f,0.f};

#pragma unroll 4
    for (int f = 0; f < NFS; f++) {
        const float wt = Wp1[(size_t)f*HID + col];
        const float wb = Wp1[(size_t)(NFS+f)*HID + col];
#pragma unroll
        for (int rr = 0; rr < 4; rr++) {
            const float hv = hrow[rr*NFS + f];
            accp[rr] = fmaf(hv, wt, accp[rr]);
            accq[rr] = fmaf(hv, wb, accq[rr]);
        }
    }
#pragma unroll
    for (int rr = 0; rr < 4; rr++) {
        g_p[(size_t)(row0 + rh*4 + rr)*HID + col] = accp[rr];
        g_q[(size_t)(row0 + rh*4 + rr)*HID + col] = accq[rr];
    }

    // a,b dots: warps 0..7 handle rows 0..7
    const int w = t >> 5, lane = t & 31;
    if (w < 8) {
        float sa = 0.f, sb_ = 0.f;
        for (int f = lane; f < NFS; f += 32) {
            const float hv = hs[w*NFS + f];
            sa  = fmaf(hv, Wa[f],     sa);
            sb_ = fmaf(hv, Wa[NFS+f], sb_);
        }
#pragma unroll
        for (int off = 16; off; off >>= 1) {
            sa  += __shfl_down_sync(0xffffffffu, sa,  off);
            sb_ += __shfl_down_sync(0xffffffffu, sb_, off);
        }
        if (lane == 0) { g_a[row0+w] = sa; g_b[row0+w] = sb_; }
    }
}

// ---------------- kernel F: fused attention + topK + MLP + output ----------
// grid = 1024 (one block per row), 256 threads.  (unchanged from round 5)
__global__ void __launch_bounds__(256) kF(
        const int*   __restrict__ z,
        const float* __restrict__ r,
        const float* __restrict__ ba_,
        const float* __restrict__ bp1,
        const float* __restrict__ Wp2,
        const float* __restrict__ bp2,
        float*       __restrict__ cout) {
    __shared__ float px[MA], py[MA], pz[MA], sbv[MA];
    __shared__ unsigned char smk[MA];
    __shared__ unsigned long long scand[64];
    __shared__ float wsum[8];
    __shared__ float satt[KK];
    __shared__ int   sidx[KK];
    __shared__ float sdx[KK], sdy[KK], sdz[KK];
    __shared__ __align__(16) float hidT[HID][KK];   // transposed: k contiguous
    __shared__ float sp[8*256];                     // per-tg matvec partials

    const int t   = threadIdx.x;
    const int row = blockIdx.x;
    const int n   = row >> 8;
    const int i   = row & (MA-1);
    const int bse = n * MA;
    const int j   = t;

    px[j]  = r[(size_t)(bse+j)*3 + 0];
    py[j]  = r[(size_t)(bse+j)*3 + 1];
    pz[j]  = r[(size_t)(bse+j)*3 + 2];
    smk[j] = (z[bse+j] > -1) ? 1 : 0;
    sbv[j] = g_b[bse+j];
    const float b1  = bp1[t];
    const float bav = ba_[0];
    const float av  = g_a[row];
    __syncthreads();

    // ---- attention score (fast math) ----
    const float dx = px[j]-px[i], dy = py[j]-py[i], dz = pz[j]-pz[i];
    const float d  = sqrtf(dx*dx + dy*dy + dz*dz);
    const bool  msk = smk[i] && smk[j] && (j != i);
    float g = 0.f;
    if (msk) {
        const float cf = 0.5f * (__cosf(fminf(d, RCf) * (PIf/RCf)) + 1.f);
        g = __expf(av + cf*sbv[j] + bav);
    }

    // ---- warp sums of g ----
    float s = g;
#pragma unroll
    for (int off = 16; off; off >>= 1) s += __shfl_xor_sync(0xffffffffu, s, off);
    if ((t & 31) == 0) wsum[t >> 5] = s;

    // ---- intra-warp exact full rank on unique u64 keys ----
    const unsigned long long key =
        (((unsigned long long)__float_as_uint(g)) << 32) | (unsigned)(MA-1-j);
    int rk = 0;
#pragma unroll
    for (int sft = 1; sft < 32; sft++) {
        const unsigned long long ok = __shfl_xor_sync(0xffffffffu, key, sft);
        rk += (ok > key);
    }
    if (rk < KK) scand[(t >> 5)*KK + rk] = key;
    __syncthreads();

    float sumg = 0.f;
#pragma unroll
    for (int w = 0; w < 8; w++) sumg += wsum[w];
    const float invsum = __fdividef(1.f, fmaxf(sumg, 1e-8f));

    // ---- warp 0: rank the 64 candidates, emit global top-8 ----
    if (t < 32) {
        const unsigned long long k0 = scand[t], k1 = scand[t + 32];
        int r0 = 0, r1 = 0;
#pragma unroll 8
        for (int m = 0; m < 64; m++) {
            const unsigned long long km = scand[m];
            r0 += (km > k0);
            r1 += (km > k1);
        }
#pragma unroll
        for (int pick = 0; pick < 2; pick++) {
            const unsigned long long kk = pick ? k1 : k0;
            const int rr = pick ? r1 : r0;
            if (rr < KK) {
                const int jw = MA - 1 - (int)(kk & 0xffffffffu);
                satt[rr] = __uint_as_float((unsigned)(kk >> 32)) * invsum;
                sidx[rr] = jw;
                const float ddx = px[jw]-px[i], ddy = py[jw]-py[i], ddz = pz[jw]-pz[i];
                const float dd  = sqrtf(ddx*ddx + ddy*ddy + ddz*ddz);
                const float inv = __fdividef(1.f, fmaxf(dd, 1e-4f));
                sdx[rr] = ddx*inv; sdy[rr] = ddy*inv; sdz[rr] = ddz*inv;
            }
        }
    }
    __syncthreads();

    // ---- MLP layer 1 -> hidT[t][k] (k contiguous) ----
    {
        const float pv = g_p[(size_t)row*HID + t];
        float xv[KK];
#pragma unroll
        for (int k = 0; k < KK; k++) {
            const float x = fmaf(satt[k], pv + g_q[(size_t)(bse + sidx[k])*HID + t], b1);
            xv[k] = __fdividef(x, 1.f + __expf(-x));   // silu
        }
        float4* dst = (float4*)&hidT[t][0];
        dst[0] = make_float4(xv[0], xv[1], xv[2], xv[3]);
        dst[1] = make_float4(xv[4], xv[5], xv[6], xv[7]);
    }
    __syncthreads();

    // ---- layer 2 matvec: thread = (o, tt-range of 32); weight loaded once,
    //      reused for all 8 k's via broadcast LDS.128 of hidT[tt][0..7] ----
    {
        const int o  = t & 31;
        const int tg = t >> 5;
        float acc[KK];
#pragma unroll
        for (int k = 0; k < KK; k++) acc[k] = 0.f;
#pragma unroll 8
        for (int u = 0; u < 32; u++) {
            const int tt = tg*32 + u;
            const float w = __ldg(&Wp2[(size_t)tt*OUTD + o]);
            const float4 h0 = *(const float4*)&hidT[tt][0];
            const float4 h1 = *(const float4*)&hidT[tt][4];
            acc[0] = fmaf(h0.x, w, acc[0]); acc[1] = fmaf(h0.y, w, acc[1]);
            acc[2] = fmaf(h0.z, w, acc[2]); acc[3] = fmaf(h0.w, w, acc[3]);
            acc[4] = fmaf(h1.x, w, acc[4]); acc[5] = fmaf(h1.y, w, acc[5]);
            acc[6] = fmaf(h1.z, w, acc[6]); acc[7] = fmaf(h1.w, w, acc[7]);
        }
#pragma unroll
        for (int k = 0; k < KK; k++) sp[tg*256 + k*32 + o] = acc[k];
    }
    __syncthreads();

    // ---- finalize: combine 8 partials, bias + direction, store ----
    {
        const int k = t >> 5;
        const int o = t & 31;
        float acc = bp2[o];
#pragma unroll
        for (int tg = 0; tg < 8; tg++) acc += sp[tg*256 + t];
        const size_t ob = ((size_t)(row*KK + k)*OUTD + o) * 3;
        cout[ob+0] = acc * sdx[k];
        cout[ob+1] = acc * sdy[k];
        cout[ob+2] = acc * sdz[k];
    }
}

// ---------------------------------------------------------------------------
extern "C" void kernel_launch(void* const* d_in, const int* in_sizes, int n_in,
                              void* d_out, int out_size) {
    const int*   z   = (const int*)  d_in[0];
    const float* r   = (const float*)d_in[1];
    const float* h   = (const float*)d_in[2];
    const float* Wa  = (const float*)d_in[3];
    const float* ba  = (const float*)d_in[4];
    const float* Wp1 = (const float*)d_in[5];
    const float* bp1 = (const float*)d_in[6];
    const float* Wp2 = (const float*)d_in[7];
    const float* bp2 = (const float*)d_in[8];

    float* out = (float*)d_out;
    const int CSZ  = Nn*MA*KK*OUTD*3;         // 786432
    const int PREF = ROWS + ROWS*3;           // 4096 (z + r)
    const int has_prefix = (out_size == CSZ + PREF) ? 1 : 0;
    float* cout = has_prefix ? (out + PREF) : out;

    kA<<<128,  512>>>(h, Wp1, Wa, z, r, out, has_prefix);
    kF<<<ROWS, 256>>>(z, r, ba, bp1, Wp2, bp2, cout);
}

// round 7
// speedup vs baseline: 1.3907x; 1.1247x over previous
#include <cuda_runtime.h>
#include <math.h>

#define Nn   4
#define MA   256
#define NFS  128
#define KK   8
#define HID  256
#define OUTD 32
#define RCf  5.0f
#define PIf  3.14159265358979323846f
#define ROWS (Nn*MA)   // 1024

#define FMA_F32X2(d, a, b, c) \
    asm("fma.rn.f32x2 %0, %1, %2, %3;" : "=l"(d) : "l"(a), "l"(b), "l"(c))
#define PACK2(d, x) \
    asm("mov.b64 %0, {%1, %1};" : "=l"(d) : "r"(__float_as_uint(x)))
#define UNPACK2(lo, hi, v) \
    asm("mov.b64 {%0, %1}, %2;" : "=r"(lo), "=r"(hi) : "l"(v))

// ---------------- scratch ---------------------------------------------------
__device__ float g_a[ROWS];
__device__ float g_b[ROWS];
__device__ float g_p[ROWS*HID];
__device__ float g_q[ROWS*HID];

// ---------------- kernel A: per-atom projections (+ output prefix) ---------
// grid = 256 (128 row-chunks x 2 col-halves), 256 threads.
// group 0 (t<128): p for its col; group 1: q for its col. 8 rows via f32x2.
__global__ void __launch_bounds__(256) kA(
        const float* __restrict__ h,
        const float* __restrict__ Wp1,
        const float* __restrict__ Wa,
        const int*   __restrict__ z,
        const float* __restrict__ r,
        float* __restrict__ out, int has_prefix) {
    __shared__ __align__(16) float hsT[NFS][8];   // [f][row], 4KB
    const int t    = threadIdx.x;
    const int row0 = (blockIdx.x >> 1) * 8;
    const int half = blockIdx.x & 1;

    if (t < NFS) {   // transpose-load h: thread t = feature t, 8 rows
        float v[8];
#pragma unroll
        for (int rr = 0; rr < 8; rr++) v[rr] = h[(size_t)(row0+rr)*NFS + t];
#pragma unroll
        for (int rr = 0; rr < 8; rr++) hsT[t][rr] = v[rr];
    }
    if (has_prefix) {
        const int gt = blockIdx.x * 256 + t;
        if (gt < ROWS)   out[gt] = (float)z[gt];
        if (gt < ROWS*3) out[ROWS + gt] = r[gt];
    }
    __syncthreads();

    const int col = half*128 + (t & 127);
    const int grp = t >> 7;                     // 0 -> p, 1 -> q
    const float* wbase = Wp1 + (size_t)(grp*NFS)*HID + col;

    unsigned long long acc[4] = {0ULL, 0ULL, 0ULL, 0ULL};  // rows (0,1)(2,3)(4,5)(6,7)

#pragma unroll 8
    for (int f = 0; f < NFS; f++) {
        const float w = __ldg(wbase + (size_t)f*HID);
        unsigned long long ww; PACK2(ww, w);
        const unsigned long long* hp = (const unsigned long long*)&hsT[f][0];
        const unsigned long long h01 = hp[0];
        const unsigned long long h23 = hp[1];
        const unsigned long long h45 = hp[2];
        const unsigned long long h67 = hp[3];
        FMA_F32X2(acc[0], h01, ww, acc[0]);
        FMA_F32X2(acc[1], h23, ww, acc[1]);
        FMA_F32X2(acc[2], h45, ww, acc[2]);
        FMA_F32X2(acc[3], h67, ww, acc[3]);
    }

    float* gdst = grp ? g_q : g_p;
#pragma unroll
    for (int pr = 0; pr < 4; pr++) {
        unsigned int lo, hi; UNPACK2(lo, hi, acc[pr]);
        gdst[(size_t)(row0 + 2*pr    )*HID + col] = __uint_as_float(lo);
        gdst[(size_t)(row0 + 2*pr + 1)*HID + col] = __uint_as_float(hi);
    }

    // a,b dots: only half==0 blocks; warp w handles row w (h read via L1)
    if (half == 0) {
        const int w = t >> 5, lane = t & 31;
        float sa = 0.f, sb_ = 0.f;
#pragma unroll
        for (int f4 = 0; f4 < NFS/32; f4++) {
            const int f = f4*32 + lane;
            const float hv = h[(size_t)(row0+w)*NFS + f];
            sa  = fmaf(hv, Wa[f],     sa);
            sb_ = fmaf(hv, Wa[NFS+f], sb_);
        }
#pragma unroll
        for (int off = 16; off; off >>= 1) {
            sa  += __shfl_down_sync(0xffffffffu, sa,  off);
            sb_ += __shfl_down_sync(0xffffffffu, sb_, off);
        }
        if (lane == 0) { g_a[row0+w] = sa; g_b[row0+w] = sb_; }
    }
}

// ---------------- kernel F: fused attention + topK + MLP + output ----------
// grid = 1024 (one block per row), 256 threads.  (FROZEN from round 5)
__global__ void __launch_bounds__(256) kF(
        const int*   __restrict__ z,
        const float* __restrict__ r,
        const float* __restrict__ ba_,
        const float* __restrict__ bp1,
        const float* __restrict__ Wp2,
        const float* __restrict__ bp2,
        float*       __restrict__ cout) {
    __shared__ float px[MA], py[MA], pz[MA], sbv[MA];
    __shared__ unsigned char smk[MA];
    __shared__ unsigned long long scand[64];
    __shared__ float wsum[8];
    __shared__ float satt[KK];
    __shared__ int   sidx[KK];
    __shared__ float sdx[KK], sdy[KK], sdz[KK];
    __shared__ __align__(16) float hidT[HID][KK];   // transposed: k contiguous
    __shared__ float sp[8*256];                     // per-tg matvec partials

    const int t   = threadIdx.x;
    const int row = blockIdx.x;
    const int n   = row >> 8;
    const int i   = row & (MA-1);
    const int bse = n * MA;
    const int j   = t;

    px[j]  = r[(size_t)(bse+j)*3 + 0];
    py[j]  = r[(size_t)(bse+j)*3 + 1];
    pz[j]  = r[(size_t)(bse+j)*3 + 2];
    smk[j] = (z[bse+j] > -1) ? 1 : 0;
    sbv[j] = g_b[bse+j];
    const float b1  = bp1[t];
    const float bav = ba_[0];
    const float av  = g_a[row];
    __syncthreads();

    // ---- attention score (fast math) ----
    const float dx = px[j]-px[i], dy = py[j]-py[i], dz = pz[j]-pz[i];
    const float d  = sqrtf(dx*dx + dy*dy + dz*dz);
    const bool  msk = smk[i] && smk[j] && (j != i);
    float g = 0.f;
    if (msk) {
        const float cf = 0.5f * (__cosf(fminf(d, RCf) * (PIf/RCf)) + 1.f);
        g = __expf(av + cf*sbv[j] + bav);
    }

    // ---- warp sums of g ----
    float s = g;
#pragma unroll
    for (int off = 16; off; off >>= 1) s += __shfl_xor_sync(0xffffffffu, s, off);
    if ((t & 31) == 0) wsum[t >> 5] = s;

    // ---- intra-warp exact full rank on unique u64 keys ----
    const unsigned long long key =
        (((unsigned long long)__float_as_uint(g)) << 32) | (unsigned)(MA-1-j);
    int rk = 0;
#pragma unroll
    for (int sft = 1; sft < 32; sft++) {
        const unsigned long long ok = __shfl_xor_sync(0xffffffffu, key, sft);
        rk += (ok > key);
    }
    if (rk < KK) scand[(t >> 5)*KK + rk] = key;
    __syncthreads();

    float sumg = 0.f;
#pragma unroll
    for (int w = 0; w < 8; w++) sumg += wsum[w];
    const float invsum = __fdividef(1.f, fmaxf(sumg, 1e-8f));

    // ---- warp 0: rank the 64 candidates, emit global top-8 ----
    if (t < 32) {
        const unsigned long long k0 = scand[t], k1 = scand[t + 32];
        int r0 = 0, r1 = 0;
#pragma unroll 8
        for (int m = 0; m < 64; m++) {
            const unsigned long long km = scand[m];
            r0 += (km > k0);
            r1 += (km > k1);
        }
#pragma unroll
        for (int pick = 0; pick < 2; pick++) {
            const unsigned long long kk = pick ? k1 : k0;
            const int rr = pick ? r1 : r0;
            if (rr < KK) {
                const int jw = MA - 1 - (int)(kk & 0xffffffffu);
                satt[rr] = __uint_as_float((unsigned)(kk >> 32)) * invsum;
                sidx[rr] = jw;
                const float ddx = px[jw]-px[i], ddy = py[jw]-py[i], ddz = pz[jw]-pz[i];
                const float dd  = sqrtf(ddx*ddx + ddy*ddy + ddz*ddz);
                const float inv = __fdividef(1.f, fmaxf(dd, 1e-4f));
                sdx[rr] = ddx*inv; sdy[rr] = ddy*inv; sdz[rr] = ddz*inv;
            }
        }
    }
    __syncthreads();

    // ---- MLP layer 1 -> hidT[t][k] (k contiguous) ----
    {
        const float pv = g_p[(size_t)row*HID + t];
        float xv[KK];
#pragma unroll
        for (int k = 0; k < KK; k++) {
            const float x = fmaf(satt[k], pv + g_q[(size_t)(bse + sidx[k])*HID + t], b1);
            xv[k] = __fdividef(x, 1.f + __expf(-x));   // silu
        }
        float4* dst = (float4*)&hidT[t][0];
        dst[0] = make_float4(xv[0], xv[1], xv[2], xv[3]);
        dst[1] = make_float4(xv[4], xv[5], xv[6], xv[7]);
    }
    __syncthreads();

    // ---- layer 2 matvec: thread = (o, tt-range of 32); weight loaded once,
    //      reused for all 8 k's via broadcast LDS.128 of hidT[tt][0..7] ----
    {
        const int o  = t & 31;
        const int tg = t >> 5;
        float acc[KK];
#pragma unroll
        for (int k = 0; k < KK; k++) acc[k] = 0.f;
#pragma unroll 8
        for (int u = 0; u < 32; u++) {
            const int tt = tg*32 + u;
            const float w = __ldg(&Wp2[(size_t)tt*OUTD + o]);
            const float4 h0 = *(const float4*)&hidT[tt][0];
            const float4 h1 = *(const float4*)&hidT[tt][4];
            acc[0] = fmaf(h0.x, w, acc[0]); acc[1] = fmaf(h0.y, w, acc[1]);
            acc[2] = fmaf(h0.z, w, acc[2]); acc[3] = fmaf(h0.w, w, acc[3]);
            acc[4] = fmaf(h1.x, w, acc[4]); acc[5] = fmaf(h1.y, w, acc[5]);
            acc[6] = fmaf(h1.z, w, acc[6]); acc[7] = fmaf(h1.w, w, acc[7]);
        }
#pragma unroll
        for (int k = 0; k < KK; k++) sp[tg*256 + k*32 + o] = acc[k];
    }
    __syncthreads();

    // ---- finalize: combine 8 partials, bias + direction, store ----
    {
        const int k = t >> 5;
        const int o = t & 31;
        float acc = bp2[o];
#pragma unroll
        for (int tg = 0; tg < 8; tg++) acc += sp[tg*256 + t];
        const size_t ob = ((size_t)(row*KK + k)*OUTD + o) * 3;
        cout[ob+0] = acc * sdx[k];
        cout[ob+1] = acc * sdy[k];
        cout[ob+2] = acc * sdz[k];
    }
}

// ---------------------------------------------------------------------------
extern "C" void kernel_launch(void* const* d_in, const int* in_sizes, int n_in,
                              void* d_out, int out_size) {
    const int*   z   = (const int*)  d_in[0];
    const float* r   = (const float*)d_in[1];
    const float* h   = (const float*)d_in[2];
    const float* Wa  = (const float*)d_in[3];
    const float* ba  = (const float*)d_in[4];
    const float* Wp1 = (const float*)d_in[5];
    const float* bp1 = (const float*)d_in[6];
    const float* Wp2 = (const float*)d_in[7];
    const float* bp2 = (const float*)d_in[8];

    float* out = (float*)d_out;
    const int CSZ  = Nn*MA*KK*OUTD*3;         // 786432
    const int PREF = ROWS + ROWS*3;           // 4096 (z + r)
    const int has_prefix = (out_size == CSZ + PREF) ? 1 : 0;
    float* cout = has_prefix ? (out + PREF) : out;

    kA<<<256,  256>>>(h, Wp1, Wa, z, r, out, has_prefix);
    kF<<<ROWS, 256>>>(z, r, ba, bp1, Wp2, bp2, cout);
}

// round 8
// speedup vs baseline: 1.3979x; 1.0052x over previous
#include <cuda_runtime.h>
#include <math.h>

#define Nn   4
#define MA   256
#define NFS  128
#define KK   8
#define HID  256
#define OUTD 32
#define RCf  5.0f
#define PIf  3.14159265358979323846f
#define ROWS (Nn*MA)   // 1024

#define FMA_F32X2(d, a, b, c) \
    asm("fma.rn.f32x2 %0, %1, %2, %3;" : "=l"(d) : "l"(a), "l"(b), "l"(c))
#define PACK2(d, x) \
    asm("mov.b64 %0, {%1, %1};" : "=l"(d) : "r"(__float_as_uint(x)))
#define UNPACK2(lo, hi, v) \
    asm("mov.b64 {%0, %1}, %2;" : "=r"(lo), "=r"(hi) : "l"(v))

// ---------------- scratch ---------------------------------------------------
__device__ float g_a[ROWS];
__device__ float g_b[ROWS];
__device__ float g_p[ROWS*HID];
__device__ float g_q[ROWS*HID];

// ---------------- kernel A: per-atom projections (+ output prefix) ---------
// grid = 256 (128 row-chunks x 2 col-halves), 256 threads.
// group 0 (t<128): p for its col; group 1: q for its col. 8 rows via f32x2.
__global__ void __launch_bounds__(256) kA(
        const float* __restrict__ h,
        const float* __restrict__ Wp1,
        const float* __restrict__ Wa,
        const int*   __restrict__ z,
        const float* __restrict__ r,
        float* __restrict__ out, int has_prefix) {
    __shared__ __align__(16) float hsT[NFS][8];   // [f][row], 4KB
    const int t    = threadIdx.x;
    const int row0 = (blockIdx.x >> 1) * 8;
    const int half = blockIdx.x & 1;

    if (t < NFS) {   // transpose-load h: thread t = feature t, 8 rows
        float v[8];
#pragma unroll
        for (int rr = 0; rr < 8; rr++) v[rr] = h[(size_t)(row0+rr)*NFS + t];
#pragma unroll
        for (int rr = 0; rr < 8; rr++) hsT[t][rr] = v[rr];
    }
    if (has_prefix) {
        const int gt = blockIdx.x * 256 + t;
        if (gt < ROWS)   out[gt] = (float)z[gt];
        if (gt < ROWS*3) out[ROWS + gt] = r[gt];
    }
    __syncthreads();

    const int col = half*128 + (t & 127);
    const int grp = t >> 7;                     // 0 -> p, 1 -> q
    const float* wbase = Wp1 + (size_t)(grp*NFS)*HID + col;

    unsigned long long acc[4] = {0ULL, 0ULL, 0ULL, 0ULL};  // rows (0,1)(2,3)(4,5)(6,7)

#pragma unroll 8
    for (int f = 0; f < NFS; f++) {
        const float w = __ldg(wbase + (size_t)f*HID);
        unsigned long long ww; PACK2(ww, w);
        const ulonglong2 hA = *(const ulonglong2*)&hsT[f][0];   // LDS.128
        const ulonglong2 hB = *(const ulonglong2*)&hsT[f][4];   // LDS.128
        FMA_F32X2(acc[0], hA.x, ww, acc[0]);
        FMA_F32X2(acc[1], hA.y, ww, acc[1]);
        FMA_F32X2(acc[2], hB.x, ww, acc[2]);
        FMA_F32X2(acc[3], hB.y, ww, acc[3]);
    }

    float* gdst = grp ? g_q : g_p;
#pragma unroll
    for (int pr = 0; pr < 4; pr++) {
        unsigned int lo, hi; UNPACK2(lo, hi, acc[pr]);
        gdst[(size_t)(row0 + 2*pr    )*HID + col] = __uint_as_float(lo);
        gdst[(size_t)(row0 + 2*pr + 1)*HID + col] = __uint_as_float(hi);
    }

    // a,b dots: only half==0 blocks; warp w handles row w (h read via L1)
    if (half == 0) {
        const int w = t >> 5, lane = t & 31;
        float sa = 0.f, sb_ = 0.f;
#pragma unroll
        for (int f4 = 0; f4 < NFS/32; f4++) {
            const int f = f4*32 + lane;
            const float hv = h[(size_t)(row0+w)*NFS + f];
            sa  = fmaf(hv, Wa[f],     sa);
            sb_ = fmaf(hv, Wa[NFS+f], sb_);
        }
#pragma unroll
        for (int off = 16; off; off >>= 1) {
            sa  += __shfl_down_sync(0xffffffffu, sa,  off);
            sb_ += __shfl_down_sync(0xffffffffu, sb_, off);
        }
        if (lane == 0) { g_a[row0+w] = sa; g_b[row0+w] = sb_; }
    }
}

// ---------------- kernel F: fused attention + topK + MLP + output ----------
// grid = 1024 (one block per row), 256 threads.
__global__ void __launch_bounds__(256) kF(
        const int*   __restrict__ z,
        const float* __restrict__ r,
        const float* __restrict__ ba_,
        const float* __restrict__ bp1,
        const float* __restrict__ Wp2,
        const float* __restrict__ bp2,
        float*       __restrict__ cout) {
    __shared__ float px[MA], py[MA], pz[MA], sbv[MA];
    __shared__ unsigned char smk[MA];
    __shared__ unsigned long long scand[64];
    __shared__ float wsum[8];
    __shared__ float satt[KK];
    __shared__ int   sidx[KK];
    __shared__ float sdx[KK], sdy[KK], sdz[KK];
    __shared__ __align__(16) float hidT[HID][KK];   // transposed: k contiguous
    __shared__ float sp[8*256];                     // per-tg matvec partials

    const int t   = threadIdx.x;
    const int row = blockIdx.x;
    const int n   = row >> 8;
    const int i   = row & (MA-1);
    const int bse = n * MA;
    const int j   = t;

    px[j]  = r[(size_t)(bse+j)*3 + 0];
    py[j]  = r[(size_t)(bse+j)*3 + 1];
    pz[j]  = r[(size_t)(bse+j)*3 + 2];
    smk[j] = (z[bse+j] > -1) ? 1 : 0;
    sbv[j] = g_b[bse+j];
    const float b1  = bp1[t];
    const float bav = ba_[0];
    const float av  = g_a[row];
    __syncthreads();

    // ---- attention score (fast math) ----
    const float dx = px[j]-px[i], dy = py[j]-py[i], dz = pz[j]-pz[i];
    const float d  = sqrtf(dx*dx + dy*dy + dz*dz);
    const bool  msk = smk[i] && smk[j] && (j != i);
    float g = 0.f;
    if (msk) {
        const float cf = 0.5f * (__cosf(fminf(d, RCf) * (PIf/RCf)) + 1.f);
        g = __expf(av + cf*sbv[j] + bav);
    }

    // ---- warp sums of g ----
    float s = g;
#pragma unroll
    for (int off = 16; off; off >>= 1) s += __shfl_xor_sync(0xffffffffu, s, off);
    if ((t & 31) == 0) wsum[t >> 5] = s;

    // ---- intra-warp exact full rank on unique u64 keys ----
    const unsigned long long key =
        (((unsigned long long)__float_as_uint(g)) << 32) | (unsigned)(MA-1-j);
    int rk = 0;
#pragma unroll
    for (int sft = 1; sft < 32; sft++) {
        const unsigned long long ok = __shfl_xor_sync(0xffffffffu, key, sft);
        rk += (ok > key);
    }
    if (rk < KK) scand[(t >> 5)*KK + rk] = key;
    __syncthreads();

    float sumg = 0.f;
#pragma unroll
    for (int w = 0; w < 8; w++) sumg += wsum[w];
    const float invsum = __fdividef(1.f, fmaxf(sumg, 1e-8f));

    // ---- warp 0: rank the 64 candidates, emit global top-8 ----
    if (t < 32) {
        const unsigned long long k0 = scand[t], k1 = scand[t + 32];
        int r0 = 0, r1 = 0;
#pragma unroll 8
        for (int m = 0; m < 64; m++) {
            const unsigned long long km = scand[m];
            r0 += (km > k0);
            r1 += (km > k1);
        }
#pragma unroll
        for (int pick = 0; pick < 2; pick++) {
            const unsigned long long kk = pick ? k1 : k0;
            const int rr = pick ? r1 : r0;
            if (rr < KK) {
                const int jw = MA - 1 - (int)(kk & 0xffffffffu);
                satt[rr] = __uint_as_float((unsigned)(kk >> 32)) * invsum;
                sidx[rr] = jw;
                const float ddx = px[jw]-px[i], ddy = py[jw]-py[i], ddz = pz[jw]-pz[i];
                const float dd  = sqrtf(ddx*ddx + ddy*ddy + ddz*ddz);
                const float inv = __fdividef(1.f, fmaxf(dd, 1e-4f));
                sdx[rr] = ddx*inv; sdy[rr] = ddy*inv; sdz[rr] = ddz*inv;
            }
        }
    }
    __syncthreads();

    // ---- MLP layer 1 -> hidT[t][k] (k contiguous) ----
    {
        const float pv = g_p[(size_t)row*HID + t];
        float xv[KK];
#pragma unroll
        for (int k = 0; k < KK; k++) {
            const float x = fmaf(satt[k], pv + g_q[(size_t)(bse + sidx[k])*HID + t], b1);
            xv[k] = __fdividef(x, 1.f + __expf(-x));   // silu
        }
        float4* dst = (float4*)&hidT[t][0];
        dst[0] = make_float4(xv[0], xv[1], xv[2], xv[3]);
        dst[1] = make_float4(xv[4], xv[5], xv[6], xv[7]);
    }
    __syncthreads();

    // ---- layer 2 matvec via f32x2: thread = (o, tt-range of 32); weight
    //      loaded once, packed, reused for all 8 k's (4 FFMA2 / u) ----
    {
        const int o  = t & 31;
        const int tg = t >> 5;
        unsigned long long a01 = 0ULL, a23 = 0ULL, a45 = 0ULL, a67 = 0ULL;
#pragma unroll 8
        for (int u = 0; u < 32; u++) {
            const int tt = tg*32 + u;
            const float w = __ldg(&Wp2[(size_t)tt*OUTD + o]);
            unsigned long long ww; PACK2(ww, w);
            const ulonglong2 hA = *(const ulonglong2*)&hidT[tt][0];   // LDS.128
            const ulonglong2 hB = *(const ulonglong2*)&hidT[tt][4];   // LDS.128
            FMA_F32X2(a01, hA.x, ww, a01);
            FMA_F32X2(a23, hA.y, ww, a23);
            FMA_F32X2(a45, hB.x, ww, a45);
            FMA_F32X2(a67, hB.y, ww, a67);
        }
        unsigned int l0,h0,l1,h1,l2,h2,l3,h3;
        UNPACK2(l0, h0, a01); UNPACK2(l1, h1, a23);
        UNPACK2(l2, h2, a45); UNPACK2(l3, h3, a67);
        sp[tg*256 + 0*32 + o] = __uint_as_float(l0);
        sp[tg*256 + 1*32 + o] = __uint_as_float(h0);
        sp[tg*256 + 2*32 + o] = __uint_as_float(l1);
        sp[tg*256 + 3*32 + o] = __uint_as_float(h1);
        sp[tg*256 + 4*32 + o] = __uint_as_float(l2);
        sp[tg*256 + 5*32 + o] = __uint_as_float(h2);
        sp[tg*256 + 6*32 + o] = __uint_as_float(l3);
        sp[tg*256 + 7*32 + o] = __uint_as_float(h3);
    }
    __syncthreads();

    // ---- finalize: combine 8 partials, bias + direction, store ----
    {
        const int k = t >> 5;
        const int o = t & 31;
        float acc = bp2[o];
#pragma unroll
        for (int tg = 0; tg < 8; tg++) acc += sp[tg*256 + t];
        const size_t ob = ((size_t)(row*KK + k)*OUTD + o) * 3;
        cout[ob+0] = acc * sdx[k];
        cout[ob+1] = acc * sdy[k];
        cout[ob+2] = acc * sdz[k];
    }
}

// ---------------------------------------------------------------------------
extern "C" void kernel_launch(void* const* d_in, const int* in_sizes, int n_in,
                              void* d_out, int out_size) {
    const int*   z   = (const int*)  d_in[0];
    const float* r   = (const float*)d_in[1];
    const float* h   = (const float*)d_in[2];
    const float* Wa  = (const float*)d_in[3];
    const float* ba  = (const float*)d_in[4];
    const float* Wp1 = (const float*)d_in[5];
    const float* bp1 = (const float*)d_in[6];
    const float* Wp2 = (const float*)d_in[7];
    const float* bp2 = (const float*)d_in[8];

    float* out = (float*)d_out;
    const int CSZ  = Nn*MA*KK*OUTD*3;         // 786432
    const int PREF = ROWS + ROWS*3;           // 4096 (z + r)
    const int has_prefix = (out_size == CSZ + PREF) ? 1 : 0;
    float* cout = has_prefix ? (out + PREF) : out;

    kA<<<256,  256>>>(h, Wp1, Wa, z, r, out, has_prefix);
    kF<<<ROWS, 256>>>(z, r, ba, bp1, Wp2, bp2, cout);
}

// round 10
// speedup vs baseline: 1.4155x; 1.0126x over previous
#include <cuda_runtime.h>
#include <math.h>

#define Nn   4
#define MA   256
#define NFS  128
#define KK   8
#define HID  256
#define OUTD 32
#define RCf  5.0f
#define PIf  3.14159265358979323846f
#define ROWS (Nn*MA)   // 1024

#define FMA_F32X2(d, a, b, c) \
    asm("fma.rn.f32x2 %0, %1, %2, %3;" : "=l"(d) : "l"(a), "l"(b), "l"(c))
#define PACK2(d, x) \
    asm("mov.b64 %0, {%1, %1};" : "=l"(d) : "r"(__float_as_uint(x)))
#define UNPACK2(lo, hi, v) \
    asm("mov.b64 {%0, %1}, %2;" : "=r"(lo), "=r"(hi) : "l"(v))

// ---------------- scratch ---------------------------------------------------
__device__ float g_a[ROWS];
__device__ float g_b[ROWS];
__device__ float g_p[ROWS*HID];
__device__ float g_q[ROWS*HID];

// ---------------- kernel A: per-atom projections (+ output prefix) ---------
// grid = 256 (128 row-chunks x 2 col-halves), 256 threads.
// group 0 (t<128): p for its col; group 1: q for its col. 8 rows via f32x2.
__global__ void __launch_bounds__(256) kA(
        const float* __restrict__ h,
        const float* __restrict__ Wp1,
        const float* __restrict__ Wa,
        const int*   __restrict__ z,
        const float* __restrict__ r,
        float* __restrict__ out, int has_prefix) {
    __shared__ __align__(16) float hsT[NFS][8];   // [f][row], 4KB
    const int t    = threadIdx.x;
    const int row0 = (blockIdx.x >> 1) * 8;
    const int half = blockIdx.x & 1;

    if (t < NFS) {   // transpose-load h: thread t = feature t, 8 rows
        float v[8];
#pragma unroll
        for (int rr = 0; rr < 8; rr++) v[rr] = h[(size_t)(row0+rr)*NFS + t];
#pragma unroll
        for (int rr = 0; rr < 8; rr++) hsT[t][rr] = v[rr];
    }
    if (has_prefix) {
        const int gt = blockIdx.x * 256 + t;
        if (gt < ROWS)   out[gt] = (float)z[gt];
        if (gt < ROWS*3) out[ROWS + gt] = r[gt];
    }
    __syncthreads();

    const int col = half*128 + (t & 127);
    const int grp = t >> 7;                     // 0 -> p, 1 -> q
    const float* wbase = Wp1 + (size_t)(grp*NFS)*HID + col;

    unsigned long long acc[4] = {0ULL, 0ULL, 0ULL, 0ULL};  // rows (0,1)(2,3)(4,5)(6,7)

#pragma unroll 8
    for (int f = 0; f < NFS; f++) {
        const float w = __ldg(wbase + (size_t)f*HID);
        unsigned long long ww; PACK2(ww, w);
        const ulonglong2 hA = *(const ulonglong2*)&hsT[f][0];   // LDS.128
        const ulonglong2 hB = *(const ulonglong2*)&hsT[f][4];   // LDS.128
        FMA_F32X2(acc[0], hA.x, ww, acc[0]);
        FMA_F32X2(acc[1], hA.y, ww, acc[1]);
        FMA_F32X2(acc[2], hB.x, ww, acc[2]);
        FMA_F32X2(acc[3], hB.y, ww, acc[3]);
    }

    float* gdst = grp ? g_q : g_p;
#pragma unroll
    for (int pr = 0; pr < 4; pr++) {
        unsigned int lo, hi; UNPACK2(lo, hi, acc[pr]);
        gdst[(size_t)(row0 + 2*pr    )*HID + col] = __uint_as_float(lo);
        gdst[(size_t)(row0 + 2*pr + 1)*HID + col] = __uint_as_float(hi);
    }

    // a,b dots: only half==0 blocks; warp w handles row w (h read via L1)
    if (half == 0) {
        const int w = t >> 5, lane = t & 31;
        float sa = 0.f, sb_ = 0.f;
#pragma unroll
        for (int f4 = 0; f4 < NFS/32; f4++) {
            const int f = f4*32 + lane;
            const float hv = h[(size_t)(row0+w)*NFS + f];
            sa  = fmaf(hv, Wa[f],     sa);
            sb_ = fmaf(hv, Wa[NFS+f], sb_);
        }
#pragma unroll
        for (int off = 16; off; off >>= 1) {
            sa  += __shfl_down_sync(0xffffffffu, sa,  off);
            sb_ += __shfl_down_sync(0xffffffffu, sb_, off);
        }
        if (lane == 0) { g_a[row0+w] = sa; g_b[row0+w] = sb_; }
    }
}

// ---------------- kernel F: fused attention + topK + MLP + output ----------
// grid = 1024 (one block per row), 256 threads. 4 barriers.
__global__ void __launch_bounds__(256) kF(
        const int*   __restrict__ z,
        const float* __restrict__ r,
        const float* __restrict__ ba_,
        const float* __restrict__ bp1,
        const float* __restrict__ Wp2,
        const float* __restrict__ bp2,
        float*       __restrict__ cout) {
    __shared__ float px[MA], py[MA], pz[MA];
    __shared__ unsigned long long scand[64];
    __shared__ float wsum[8];
    __shared__ float satt[KK];
    __shared__ int   sidx[KK];
    __shared__ float sdx[KK], sdy[KK], sdz[KK];
    __shared__ __align__(16) float hidT[HID][KK];   // transposed: k contiguous
    __shared__ float sp[8*256];                     // per-tg matvec partials

    const int t   = threadIdx.x;
    const int row = blockIdx.x;
    const int n   = row >> 8;
    const int i   = row & (MA-1);
    const int bse = n * MA;
    const int j   = t;

    // early prefetch: p_i column (consumed only after top-K)
    const float pv = g_p[(size_t)row*HID + t];
    const float b1 = bp1[t];

    // own-j loads (coalesced) + broadcast i loads; stage positions for warp0
    const float rjx = r[(size_t)(bse+j)*3 + 0];
    const float rjy = r[(size_t)(bse+j)*3 + 1];
    const float rjz = r[(size_t)(bse+j)*3 + 2];
    const float rix = __ldg(&r[(size_t)(bse+i)*3 + 0]);
    const float riy = __ldg(&r[(size_t)(bse+i)*3 + 1]);
    const float riz = __ldg(&r[(size_t)(bse+i)*3 + 2]);
    const int   zj  = z[bse+j];
    const int   zi  = __ldg(&z[bse+i]);
    const float bj  = g_b[bse+j];
    const float av  = __ldg(&g_a[row]);
    const float bav = __ldg(&ba_[0]);
    px[j] = rjx; py[j] = rjy; pz[j] = rjz;   // ordered before warp0 use by the
                                             // barrier after scand below

    // ---- attention score (R8 semantics: av + cf*bj + bav) ----
    const float dx = rjx-rix, dy = rjy-riy, dz = rjz-riz;
    const float d  = sqrtf(dx*dx + dy*dy + dz*dz);
    const bool  msk = (zi > -1) && (zj > -1) && (j != i);
    float g = 0.f;
    if (msk) {
        const float cf = 0.5f * (__cosf(fminf(d, RCf) * (PIf/RCf)) + 1.f);
        g = __expf(av + cf*bj + bav);
    }

    // ---- warp sums of g ----
    float s = g;
#pragma unroll
    for (int off = 16; off; off >>= 1) s += __shfl_xor_sync(0xffffffffu, s, off);
    if ((t & 31) == 0) wsum[t >> 5] = s;

    // ---- intra-warp exact full rank on unique u64 keys ----
    const unsigned long long key =
        (((unsigned long long)__float_as_uint(g)) << 32) | (unsigned)(MA-1-j);
    int rk = 0;
#pragma unroll
    for (int sft = 1; sft < 32; sft++) {
        const unsigned long long ok = __shfl_xor_sync(0xffffffffu, key, sft);
        rk += (ok > key);
    }
    if (rk < KK) scand[(t >> 5)*KK + rk] = key;
    __syncthreads();

    // ---- warp 0: rank the 64 candidates, emit global top-8 ----
    if (t < 32) {
        float sumg = 0.f;
#pragma unroll
        for (int w = 0; w < 8; w++) sumg += wsum[w];
        const float invsum = __fdividef(1.f, fmaxf(sumg, 1e-8f));

        const unsigned long long k0 = scand[t], k1 = scand[t + 32];
        int r0 = 0, r1 = 0;
#pragma unroll 8
        for (int m = 0; m < 64; m++) {
            const unsigned long long km = scand[m];
            r0 += (km > k0);
            r1 += (km > k1);
        }
#pragma unroll
        for (int pick = 0; pick < 2; pick++) {
            const unsigned long long kk = pick ? k1 : k0;
            const int rr = pick ? r1 : r0;
            if (rr < KK) {
                const int jw = MA - 1 - (int)(kk & 0xffffffffu);
                satt[rr] = __uint_as_float((unsigned)(kk >> 32)) * invsum;
                sidx[rr] = jw;
                const float ddx = px[jw]-rix, ddy = py[jw]-riy, ddz = pz[jw]-riz;
                const float dd  = sqrtf(ddx*ddx + ddy*ddy + ddz*ddz);
                const float inv = __fdividef(1.f, fmaxf(dd, 1e-4f));
                sdx[rr] = ddx*inv; sdy[rr] = ddy*inv; sdz[rr] = ddz*inv;
            }
        }
    }
    __syncthreads();

    // ---- MLP layer 1 -> hidT[t][k] (k contiguous) ----
    {
        float xv[KK];
#pragma unroll
        for (int k = 0; k < KK; k++) {
            const float x = fmaf(satt[k], pv + g_q[(size_t)(bse + sidx[k])*HID + t], b1);
            xv[k] = __fdividef(x, 1.f + __expf(-x));   // silu
        }
        float4* dst = (float4*)&hidT[t][0];
        dst[0] = make_float4(xv[0], xv[1], xv[2], xv[3]);
        dst[1] = make_float4(xv[4], xv[5], xv[6], xv[7]);
    }
    __syncthreads();

    // ---- layer 2 matvec via f32x2: thread = (o, tt-range of 32) ----
    {
        const int o  = t & 31;
        const int tg = t >> 5;
        unsigned long long a01 = 0ULL, a23 = 0ULL, a45 = 0ULL, a67 = 0ULL;
#pragma unroll 8
        for (int u = 0; u < 32; u++) {
            const int tt = tg*32 + u;
            const float w = __ldg(&Wp2[(size_t)tt*OUTD + o]);
            unsigned long long ww; PACK2(ww, w);
            const ulonglong2 hA = *(const ulonglong2*)&hidT[tt][0];   // LDS.128
            const ulonglong2 hB = *(const ulonglong2*)&hidT[tt][4];   // LDS.128
            FMA_F32X2(a01, hA.x, ww, a01);
            FMA_F32X2(a23, hA.y, ww, a23);
            FMA_F32X2(a45, hB.x, ww, a45);
            FMA_F32X2(a67, hB.y, ww, a67);
        }
        unsigned int l0,h0,l1,h1,l2,h2,l3,h3;
        UNPACK2(l0, h0, a01); UNPACK2(l1, h1, a23);
        UNPACK2(l2, h2, a45); UNPACK2(l3, h3, a67);
        sp[tg*256 + 0*32 + o] = __uint_as_float(l0);
        sp[tg*256 + 1*32 + o] = __uint_as_float(h0);
        sp[tg*256 + 2*32 + o] = __uint_as_float(l1);
        sp[tg*256 + 3*32 + o] = __uint_as_float(h1);
        sp[tg*256 + 4*32 + o] = __uint_as_float(l2);
        sp[tg*256 + 5*32 + o] = __uint_as_float(h2);
        sp[tg*256 + 6*32 + o] = __uint_as_float(l3);
        sp[tg*256 + 7*32 + o] = __uint_as_float(h3);
    }
    __syncthreads();

    // ---- finalize: combine 8 partials, bias + direction, store ----
    {
        const int k = t >> 5;
        const int o = t & 31;
        float acc = bp2[o];
#pragma unroll
        for (int tg = 0; tg < 8; tg++) acc += sp[tg*256 + t];
        const size_t ob = ((size_t)(row*KK + k)*OUTD + o) * 3;
        cout[ob+0] = acc * sdx[k];
        cout[ob+1] = acc * sdy[k];
        cout[ob+2] = acc * sdz[k];
    }
}

// ---------------------------------------------------------------------------
extern "C" void kernel_launch(void* const* d_in, const int* in_sizes, int n_in,
                              void* d_out, int out_size) {
    const int*   z   = (const int*)  d_in[0];
    const float* r   = (const float*)d_in[1];
    const float* h   = (const float*)d_in[2];
    const float* Wa  = (const float*)d_in[3];
    const float* ba  = (const float*)d_in[4];
    const float* Wp1 = (const float*)d_in[5];
    const float* bp1 = (const float*)d_in[6];
    const float* Wp2 = (const float*)d_in[7];
    const float* bp2 = (const float*)d_in[8];

    float* out = (float*)d_out;
    const int CSZ  = Nn*MA*KK*OUTD*3;         // 786432
    const int PREF = ROWS + ROWS*3;           // 4096 (z + r)
    const int has_prefix = (out_size == CSZ + PREF) ? 1 : 0;
    float* cout = has_prefix ? (out + PREF) : out;

    kA<<<256,  256>>>(h, Wp1, Wa, z, r, out, has_prefix);
    kF<<<ROWS, 256>>>(z, r, ba, bp1, Wp2, bp2, cout);
}